// round 8
// baseline (speedup 1.0000x reference)
#include <cuda_runtime.h>
#include <stdint.h>

// x: [B=16, C=128, H=224, W=224] fp32, perm: [B=16, 16] int32
// G=4, block = 56x56 per image plane. Output block o <- input block inv_perm[o].
//
// 256-bit access version (sm_100+ ld/st.global.v8.b32).
// Unit = 32B chunk. Row = 896B = 28 chunks. Segment = 224B = 7 chunks,
// always 32B-aligned (224 % 32 == 0).
//
// Geometry: grid = (4, C, B); blockIdx.x = output block-row i (no div!).
// blockDim = (28, 8) = 224 threads = exactly 7 warps.
//   threadIdx.x = chunk column 0..27  ->  j = x/7, wj = x%7
//   threadIdx.y picks a 7-row group; thread copies 7 rows (7 front-batched
//   256-bit streaming loads, then 7 streaming stores). 8*7 = 56 rows = one
//   full output block-row slab per CTA.
//
// Cache policy (validated R3 vs R4/R5): evict-first (.cs) on BOTH streams.

#define G2 16

__global__ __launch_bounds__(224) void block_shuffle_kernel(
    const uint4* __restrict__ x,      // addressed in 32B chunks via PTX
    const int*   __restrict__ perm,
    uint4*       __restrict__ out)
{
    __shared__ int s_inv[G2];

    const int i = blockIdx.x;          // output block row 0..3
    const int c = blockIdx.y;
    const int b = blockIdx.z;

    const int tid = threadIdx.y * 28 + threadIdx.x;
    if (tid < G2) {
        // perm[b][k] = o  (output slot of input block k)  ->  inv[o] = k
        const int o = perm[b * G2 + tid];
        s_inv[o] = tid;
    }
    __syncthreads();

    const int tx = threadIdx.x;        // 0..27
    const int j  = tx / 7;             // output block col
    const int wj = tx - j * 7;         // chunk within segment

    const int k  = s_inv[i * 4 + j];
    const int si = k >> 2;
    const int sj = k & 3;

    const int r0 = threadIdx.y * 7;                    // 0,7,...,49
    const long plane = ((long)(b * 128 + c)) * 224 * 28;   // in 32B chunks

    // byte addresses (all 32B-aligned)
    const char* src = (const char*)x   + (plane + (long)(si * 56 + r0) * 28 + sj * 7 + wj) * 32;
    char*       dst = (char*)out       + (plane + (long)(i  * 56 + r0) * 28 + tx)          * 32;

    unsigned v[7][8];

    // 7 independent 256-bit streaming loads (front-batched)
    #pragma unroll
    for (int q = 0; q < 7; q++) {
        asm volatile(
            "ld.global.cs.v8.b32 {%0,%1,%2,%3,%4,%5,%6,%7}, [%8];"
            : "=r"(v[q][0]), "=r"(v[q][1]), "=r"(v[q][2]), "=r"(v[q][3]),
              "=r"(v[q][4]), "=r"(v[q][5]), "=r"(v[q][6]), "=r"(v[q][7])
            : "l"(src + (long)q * 896));
    }

    // 7 256-bit streaming stores
    #pragma unroll
    for (int q = 0; q < 7; q++) {
        asm volatile(
            "st.global.cs.v8.b32 [%8], {%0,%1,%2,%3,%4,%5,%6,%7};"
            :: "r"(v[q][0]), "r"(v[q][1]), "r"(v[q][2]), "r"(v[q][3]),
               "r"(v[q][4]), "r"(v[q][5]), "r"(v[q][6]), "r"(v[q][7]),
               "l"(dst + (long)q * 896)
            : "memory");
    }
}

extern "C" void kernel_launch(void* const* d_in, const int* in_sizes, int n_in,
                              void* d_out, int out_size)
{
    const uint4* x    = (const uint4*)d_in[0];
    const int*   perm = (const int*)d_in[1];
    uint4*       out  = (uint4*)d_out;

    dim3 grid(4, 128, 16);    // (block-row, C, B)
    dim3 block(28, 8);        // 224 threads = 7 warps
    block_shuffle_kernel<<<grid, block>>>(x, perm, out);
}

// round 9
// speedup vs baseline: 1.0127x; 1.0127x over previous
#include <cuda_runtime.h>
#include <stdint.h>

// x: [B=16, C=128, H=224, W=224] fp32, perm: [B=16, 16] int32
// G=4, block = 56x56 per image plane. Output block o <- input block inv_perm[o].
//
// Proven-best geometry (R3/R6): grid = (H/32, C, B) = (7, 128, 16),
// blockDim = (56, 4). Each (blockIdx.x, threadIdx.y) handles an 8-row group;
// 56 % 8 == 0 keeps all 8 rows in one output block row, so perm lookup and
// index math amortize 8x with 8 front-batched independent loads (MLP=8).
//
// Cache policy: evict-first (.cs) both streams (validated vs R4/R5).
// New in this round: .L2::256B promotion hint on loads — adjacent 224B read
// segments are consumed by concurrent CTAs, so larger L2 fill requests give
// the DRAM controller longer sequential read bursts.

#define G2 16

__device__ __forceinline__ float4 ldcs_256b(const float4* p) {
    float4 v;
    asm volatile("ld.global.cs.L2::256B.v4.f32 {%0,%1,%2,%3}, [%4];"
                 : "=f"(v.x), "=f"(v.y), "=f"(v.z), "=f"(v.w) : "l"(p));
    return v;
}

__global__ __launch_bounds__(224) void block_shuffle_kernel(
    const float4* __restrict__ x,
    const int*    __restrict__ perm,
    float4*       __restrict__ out)
{
    __shared__ int s_inv[G2];

    const int b = blockIdx.z;
    const int c = blockIdx.y;

    const int tid = threadIdx.y * 56 + threadIdx.x;
    if (tid < G2) {
        // perm[b][k] = o  (output slot of input block k)  ->  inv[o] = k
        const int o = perm[b * G2 + tid];
        s_inv[o] = tid;
    }
    __syncthreads();

    const int w4 = threadIdx.x;                              // 0..55
    const int h0 = (blockIdx.x * 4 + threadIdx.y) * 8;       // 0,8,...,216

    const int j = w4 / 14;          // output block col (const-div -> mul)
    const int i = h0 / 56;          // output block row (constant over 8 rows)
    const int k = s_inv[i * 4 + j];
    const int si = k >> 2;
    const int sj = k & 3;

    const int sh0 = si * 56 + (h0 - i * 56);
    const int sw4 = sj * 14 + (w4 - j * 14);

    const int plane = (b * 128 + c) * 224;                   // row base (in rows)
    const float4* __restrict__ src = x   + ((long)(plane + sh0)) * 56 + sw4;
    float4*       __restrict__ dst = out + ((long)(plane + h0 )) * 56 + w4;

    // 8 independent streaming loads (front-batched, 256B L2 promotion)
    float4 v0 = ldcs_256b(src);
    float4 v1 = ldcs_256b(src +  56);
    float4 v2 = ldcs_256b(src + 112);
    float4 v3 = ldcs_256b(src + 168);
    float4 v4 = ldcs_256b(src + 224);
    float4 v5 = ldcs_256b(src + 280);
    float4 v6 = ldcs_256b(src + 336);
    float4 v7 = ldcs_256b(src + 392);

    __stcs(dst,       v0);
    __stcs(dst +  56, v1);
    __stcs(dst + 112, v2);
    __stcs(dst + 168, v3);
    __stcs(dst + 224, v4);
    __stcs(dst + 280, v5);
    __stcs(dst + 336, v6);
    __stcs(dst + 392, v7);
}

extern "C" void kernel_launch(void* const* d_in, const int* in_sizes, int n_in,
                              void* d_out, int out_size)
{
    const float4* x    = (const float4*)d_in[0];
    const int*    perm = (const int*)d_in[1];
    float4*       out  = (float4*)d_out;

    dim3 grid(224 / 32, 128, 16);   // (7, C, B)
    dim3 block(56, 4);
    block_shuffle_kernel<<<grid, block>>>(x, perm, out);
}